// round 16
// baseline (speedup 1.0000x reference)
#include <cuda_runtime.h>
#include <math.h>
#include <stdint.h>

// Problem constants
#define Bsz 4
#define Tn  2048
#define Cn  1024
#define Hn  8
#define Dn  128
#define DffN 4096
#define Mrows (Bsz*Tn)   // 8192
#define SCALE 11.313708498984761f  // sqrt(128), multiply (faithful to reference)

// ---------------- scratch ----------------
__device__ float g_h [(size_t)Mrows*Cn];
__device__ float g_q [(size_t)Mrows*Cn];
__device__ float g_k [(size_t)Mrows*Cn];
__device__ float g_v [(size_t)Mrows*Cn];
__device__ float g_x1[(size_t)Mrows*Cn];
__device__ float g_h2[(size_t)Mrows*Cn];
__device__ float g_ff[(size_t)Mrows*DffN];

// ---------------- helpers ----------------
__device__ __forceinline__ uint32_t cvt_tf32(float x){
    uint32_t u; asm("cvt.rna.tf32.f32 %0, %1;" : "=r"(u) : "f"(x)); return u;
}
__device__ __forceinline__ void mma8(float* d, const uint32_t* a, const uint32_t* b){
    asm volatile("mma.sync.aligned.m16n8k8.row.col.f32.tf32.tf32.f32 "
        "{%0,%1,%2,%3},{%4,%5,%6,%7},{%8,%9},{%0,%1,%2,%3};"
        : "+f"(d[0]),"+f"(d[1]),"+f"(d[2]),"+f"(d[3])
        : "r"(a[0]),"r"(a[1]),"r"(a[2]),"r"(a[3]),"r"(b[0]),"r"(b[1]));
}

// ---------------- LayerNorm ----------------
__global__ __launch_bounds__(256) void ln_kernel(
    const float* __restrict__ x, const float* __restrict__ g,
    const float* __restrict__ bta, float* __restrict__ out)
{
    long row = blockIdx.x;
    int tid = threadIdx.x;
    const float4* xr = (const float4*)(x + row*(long)Cn);
    float4 v = xr[tid];
    float s = v.x + v.y + v.z + v.w;

    __shared__ float sh[34];
    int lane = tid & 31, wid = tid >> 5;
    #pragma unroll
    for (int o = 16; o > 0; o >>= 1) s += __shfl_xor_sync(0xffffffffu, s, o);
    if (lane == 0) sh[wid] = s;
    __syncthreads();
    if (tid == 0) {
        float t = 0.f;
        #pragma unroll
        for (int w = 0; w < 8; w++) t += sh[w];
        sh[32] = t * (1.0f / Cn);
    }
    __syncthreads();
    float mu = sh[32];
    float dx0 = v.x - mu, dx1 = v.y - mu, dx2 = v.z - mu, dx3 = v.w - mu;
    float ss = dx0*dx0 + dx1*dx1 + dx2*dx2 + dx3*dx3;
    #pragma unroll
    for (int o = 16; o > 0; o >>= 1) ss += __shfl_xor_sync(0xffffffffu, ss, o);
    __syncthreads();
    if (lane == 0) sh[wid] = ss;
    __syncthreads();
    if (tid == 0) {
        float t = 0.f;
        #pragma unroll
        for (int w = 0; w < 8; w++) t += sh[w];
        sh[33] = rsqrtf(t * (1.0f / Cn) + 1e-5f);
    }
    __syncthreads();
    float rstd = sh[33];
    float4 gg = ((const float4*)g)[tid];
    float4 bb = ((const float4*)bta)[tid];
    float4 o4;
    o4.x = dx0 * rstd * gg.x + bb.x;
    o4.y = dx1 * rstd * gg.y + bb.y;
    o4.z = dx2 * rstd * gg.z + bb.z;
    o4.w = dx3 * rstd * gg.w + bb.w;
    ((float4*)(out + row*(long)Cn))[tid] = o4;
}

// ---------------- TF32 MMA GEMM (round-8 proven; unchanged) ----------------
template<int SPLIT>
__global__ __launch_bounds__(256, 2) void mma_gemm(
    const float* __restrict__ A, const float* __restrict__ Bm, float* __restrict__ Cm,
    int M, int N, int K, int lda, int ldb, int ldc,
    long sB, long sC,
    const float* __restrict__ bias, int applyRelu,
    const float* __restrict__ res, int ldres)
{
    constexpr int AW = 2048;
    constexpr int BW = 2112;
    constexpr int oAl = AW;
    constexpr int oBh = (SPLIT==3) ? 2*AW : AW;
    constexpr int oBl = oBh + BW;
    constexpr int NTW = (SPLIT==3) ? (2*AW + 2*BW) : (AW + BW);
    extern __shared__ uint32_t smem[];

    int bz = blockIdx.z;
    Bm += bz * sB;
    Cm += bz * sC;

    int brow = blockIdx.y*128, bcol = blockIdx.x*128;
    int tid = threadIdx.x, lane = tid&31, wid = tid>>5;
    int wm = wid>>2, wn = wid&3;
    int lsw = lane ^ (lane>>2);

    float acc[4][4][4];
    #pragma unroll
    for (int i=0;i<4;i++)
        #pragma unroll
        for (int j=0;j<4;j++)
            #pragma unroll
            for (int t=0;t<4;t++) acc[i][j][t]=0.f;

    int a_r0 = tid>>2;
    int a_k0 = (tid&3)*4;
    const float* Ap = A + (long)(brow + a_r0)*lda + a_k0;
    int b_k0 = tid>>5;
    int b_c0 = lane*4;
    const float* Bp = Bm + (long)b_k0*ldb + bcol + b_c0;

    float4 av0, av1, bv0, bv1;

    auto gload = [&](){
        av0 = *(const float4*)(Ap);
        av1 = *(const float4*)(Ap + (long)64*lda);
        bv0 = *(const float4*)(Bp);
        bv1 = *(const float4*)(Bp + (long)8*ldb);
        Ap += 16; Bp += (long)16*ldb;
    };

    int st_rr  = a_r0 & 15;
    int st_r4a = a_r0 >> 4;
    int st_r4b = (a_r0 + 64) >> 4;
    int st_wk  = (tid & 1) * 2;
    int st_rb  = (st_rr >> 3) & 1;
    int st_bk3 = b_k0 & 3;
    int st_bw  = (b_k0 >> 2) & 1;

    auto store_tile = [&](uint32_t* base){
        uint32_t* Ah = base;
        uint32_t* Al = base + oAl;
        uint32_t* Bh = base + oBh;
        uint32_t* Bl = base + oBl;
        float va[4] = {av0.x,av0.y,av0.z,av0.w};
        float vb[4] = {av1.x,av1.y,av1.z,av1.w};
        #pragma unroll
        for (int j=0;j<4;j++){
            int k  = a_k0 + j;
            int l  = ((st_rr&7)<<2) | j;
            int ls = l ^ (st_rr&7);
            int w  = st_wk + st_rb;
            int idA = (k>>3)*1024 + ls*4 + w;
            uint32_t h0 = cvt_tf32(va[j]);
            Ah[idA + st_r4a*128] = h0;
            uint32_t h1 = cvt_tf32(vb[j]);
            Ah[idA + st_r4b*128] = h1;
            if (SPLIT==3){
                Al[idA + st_r4a*128] = cvt_tf32(va[j]-__uint_as_float(h0));
                Al[idA + st_r4b*128] = cvt_tf32(vb[j]-__uint_as_float(h1));
            }
        }
        float wa[4] = {bv0.x,bv0.y,bv0.z,bv0.w};
        float wb[4] = {bv1.x,bv1.y,bv1.z,bv1.w};
        #pragma unroll
        for (int j=0;j<4;j++){
            int n = b_c0 + j;
            int l = ((n&7)<<2) | st_bk3;
            int idB = (n>>3)*66 + l*2 + st_bw;
            uint32_t h0 = cvt_tf32(wa[j]);
            Bh[idB] = h0;
            uint32_t h1 = cvt_tf32(wb[j]);
            Bh[idB + 1056] = h1;
            if (SPLIT==3){
                Bl[idB]        = cvt_tf32(wa[j]-__uint_as_float(h0));
                Bl[idB + 1056] = cvt_tf32(wb[j]-__uint_as_float(h1));
            }
        }
    };

    auto compute_tile = [&](const uint32_t* base){
        const uint32_t* Ah = base;
        const uint32_t* Al = base + oAl;
        const uint32_t* Bh = base + oBh;
        const uint32_t* Bl = base + oBl;
        #pragma unroll
        for (int kg = 0; kg < 2; kg++){
            uint32_t bhf[4][2], blf[4][2];
            #pragma unroll
            for (int nt=0;nt<4;nt++){
                uint2 t = *(const uint2*)(Bh + kg*1056 + (wn*4+nt)*66 + lane*2);
                bhf[nt][0]=t.x; bhf[nt][1]=t.y;
                if (SPLIT==3){
                    uint2 u = *(const uint2*)(Bl + kg*1056 + (wn*4+nt)*66 + lane*2);
                    blf[nt][0]=u.x; blf[nt][1]=u.y;
                }
            }
            #pragma unroll
            for (int mt=0;mt<4;mt++){
                uint4 a4 = *(const uint4*)(Ah + kg*1024 + (wm*4+mt)*128 + lsw*4);
                uint32_t ah[4] = {a4.x,a4.y,a4.z,a4.w};
                uint32_t alr[4];
                if (SPLIT==3){
                    uint4 l4 = *(const uint4*)(Al + kg*1024 + (wm*4+mt)*128 + lsw*4);
                    alr[0]=l4.x; alr[1]=l4.y; alr[2]=l4.z; alr[3]=l4.w;
                }
                #pragma unroll
                for (int nt=0;nt<4;nt++){
                    mma8(acc[mt][nt], ah, bhf[nt]);
                    if (SPLIT==3){
                        mma8(acc[mt][nt], ah, blf[nt]);
                        mma8(acc[mt][nt], alr, bhf[nt]);
                    }
                }
            }
        }
    };

    gload();
    store_tile(smem);
    __syncthreads();

    int nIter = K >> 4;
    for (int i = 0; i < nIter; i++) {
        uint32_t* cur = smem + (size_t)(i & 1) * NTW;
        uint32_t* nxt = smem + (size_t)((i & 1) ^ 1) * NTW;
        bool hasNext = (i + 1 < nIter);
        if (hasNext) gload();
        compute_tile(cur);
        if (hasNext) store_tile(nxt);
        __syncthreads();
    }

    #pragma unroll
    for (int mt=0;mt<4;mt++){
        int r0 = brow + wm*64 + mt*16 + (lane>>2);
        #pragma unroll
        for (int nt=0;nt<4;nt++){
            int c = bcol + wn*32 + nt*8 + (lane&3)*2;
            float2 v0 = make_float2(acc[mt][nt][0], acc[mt][nt][1]);
            float2 v1 = make_float2(acc[mt][nt][2], acc[mt][nt][3]);
            if (bias){
                float b0=bias[c], b1=bias[c+1];
                v0.x+=b0; v0.y+=b1; v1.x+=b0; v1.y+=b1;
            }
            if (applyRelu){
                v0.x=fmaxf(v0.x,0.f); v0.y=fmaxf(v0.y,0.f);
                v1.x=fmaxf(v1.x,0.f); v1.y=fmaxf(v1.y,0.f);
            }
            if (res){
                v0.x += res[(long)r0*ldres + c];     v0.y += res[(long)r0*ldres + c+1];
                v1.x += res[(long)(r0+8)*ldres + c]; v1.y += res[(long)(r0+8)*ldres + c+1];
            }
            *(float2*)(Cm + (long)r0*ldc + c)     = v0;
            *(float2*)(Cm + (long)(r0+8)*ldc + c) = v1;
        }
    }
}

// ---------------- Warp-specialized flash attention: 128-row Q tiles ----------------
// 384 threads: warps 0-7 consumers (16 Q rows each = 128 rows/CTA), warps 8-11
// producers (32-row K/V tiles, single buffer, uint4 commits). Grid halves to
// 512 CTAs -> 3.46 waves (was 7). Named barriers count=384:
//   READY=1 (producers arrive, consumers sync), FREE=2 (consumers arrive, producers sync).
// Producer prefetches kt+1 into registers right after arrive(READY).
#define QTrows 128
#define QSd 132
#define KSd 132
#define VSd 136
#define PSd 36
#define QH_OFF 0
#define QL_OFF (QTrows*QSd)              // 16896
#define KH_OFF (2*QTrows*QSd)            // 33792
#define KL_OFF (KH_OFF + 32*KSd)         // 38016
#define VT_OFF (KL_OFF + 32*KSd)         // 42240
#define PW_OFF (VT_OFF + 32*VSd)         // 46592
#define ATTN_WORDS (PW_OFF + 8*16*PSd)   // 51200
#define ATTN_BYTES (ATTN_WORDS*4)        // 204800 B

__global__ __launch_bounds__(384, 1) void attn_ws(
    const float* __restrict__ Q, const float* __restrict__ K, const float* __restrict__ V,
    const float* __restrict__ x, float* __restrict__ x1)
{
    extern __shared__ uint32_t sm[];
    uint32_t* Qh = sm + QH_OFF;
    uint32_t* Ql = sm + QL_OFF;
    uint32_t* Kh = sm + KH_OFF;
    uint32_t* Kl = sm + KL_OFF;
    uint32_t* Vt = sm + VT_OFF;
    uint32_t* Pw = sm + PW_OFF;

    int bh = blockIdx.y; int b = bh>>3, h = bh&7;
    int q0 = blockIdx.x*QTrows;
    int tid = threadIdx.x, lane = tid&31, wid = tid>>5;

    const float* Qg = Q + ((long)b*Tn + q0)*Cn + h*Dn;
    const float* Kg = K + (long)b*Tn*Cn + h*Dn;
    const float* Vg = V + (long)b*Tn*Cn + h*Dn;

    // All 384 threads: load + split Q tile (128x128) into smem
    for (int idx = tid; idx < QTrows*32; idx += 384){
        int r = idx>>5, c = (idx&31)*4;
        float4 t = *(const float4*)(Qg + (long)r*Cn + c);
        uint4 hi, lo;
        hi.x=cvt_tf32(t.x); lo.x=cvt_tf32(t.x-__uint_as_float(hi.x));
        hi.y=cvt_tf32(t.y); lo.y=cvt_tf32(t.y-__uint_as_float(hi.y));
        hi.z=cvt_tf32(t.z); lo.z=cvt_tf32(t.z-__uint_as_float(hi.z));
        hi.w=cvt_tf32(t.w); lo.w=cvt_tf32(t.w-__uint_as_float(hi.w));
        *(uint4*)(&Qh[r*QSd + c]) = hi;
        *(uint4*)(&Ql[r*QSd + c]) = lo;
    }
    __syncthreads();

    if (wid >= 8) {
        // ================= PRODUCER (warps 8-11) =================
        int p = tid - 256;   // 0..127
        float4 kr[8], vr[8];
        // prefetch kt=0
        #pragma unroll
        for (int i=0;i<8;i++){
            int idx = p + i*128;
            int r = idx>>5, c = (idx&31)*4;
            kr[i] = *(const float4*)(Kg + (long)r*Cn + c);
            vr[i] = *(const float4*)(Vg + (long)r*Cn + c);
        }
        for (int kt = 0; kt < Tn/32; kt++){
            if (kt >= 1)
                asm volatile("bar.sync 2, 384;" ::: "memory");
            #pragma unroll
            for (int i=0;i<8;i++){
                int idx = p + i*128;
                int r = idx>>5, c = (idx&31)*4;
                uint4 hi, lo;
                hi.x=cvt_tf32(kr[i].x); lo.x=cvt_tf32(kr[i].x-__uint_as_float(hi.x));
                hi.y=cvt_tf32(kr[i].y); lo.y=cvt_tf32(kr[i].y-__uint_as_float(hi.y));
                hi.z=cvt_tf32(kr[i].z); lo.z=cvt_tf32(kr[i].z-__uint_as_float(hi.z));
                hi.w=cvt_tf32(kr[i].w); lo.w=cvt_tf32(kr[i].w-__uint_as_float(hi.w));
                *(uint4*)(&Kh[r*KSd + c]) = hi;
                *(uint4*)(&Kl[r*KSd + c]) = lo;
                uint4 vv;
                vv.x=cvt_tf32(vr[i].x); vv.y=cvt_tf32(vr[i].y);
                vv.z=cvt_tf32(vr[i].z); vv.w=cvt_tf32(vr[i].w);
                *(uint4*)(&Vt[r*VSd + c]) = vv;
            }
            asm volatile("bar.arrive 1, 384;" ::: "memory");
            // prefetch next tile into registers (overlaps consumer compute)
            if (kt + 1 < Tn/32){
                const float* Ksrc = Kg + (long)(kt+1)*32*Cn;
                const float* Vsrc = Vg + (long)(kt+1)*32*Cn;
                #pragma unroll
                for (int i=0;i<8;i++){
                    int idx = p + i*128;
                    int r = idx>>5, c = (idx&31)*4;
                    kr[i] = *(const float4*)(Ksrc + (long)r*Cn + c);
                    vr[i] = *(const float4*)(Vsrc + (long)r*Cn + c);
                }
            }
        }
    } else {
        // ================= CONSUMER (warps 0-7, 16 rows each) =================
        int r0 = lane>>2, j = lane&3;
        const uint32_t* Qhw = Qh + (wid*16)*QSd;
        const uint32_t* Qlw = Ql + (wid*16)*QSd;
        uint32_t* Pww = Pw + wid*(16*PSd);

        float accO[16][4];
        #pragma unroll
        for (int i=0;i<16;i++)
            #pragma unroll
            for (int t=0;t<4;t++) accO[i][t]=0.f;
        float rm0 = -1e30f, rm1 = -1e30f, rl0 = 0.f, rl1 = 0.f;

        for (int kt = 0; kt < Tn/32; kt++){
            asm volatile("bar.sync 1, 384;" ::: "memory");

            // S = Q K^T (3xTF32): warp tile 16x32
            float accS[4][4];
            #pragma unroll
            for (int i=0;i<4;i++)
                #pragma unroll
                for (int t=0;t<4;t++) accS[i][t]=0.f;

            #pragma unroll 4
            for (int kg=0; kg<16; kg++){
                int kk = kg*8 + j;
                uint32_t ah[4], al[4];
                ah[0]=Qhw[r0*QSd+kk];     ah[1]=Qhw[(r0+8)*QSd+kk];
                ah[2]=Qhw[r0*QSd+kk+4];   ah[3]=Qhw[(r0+8)*QSd+kk+4];
                al[0]=Qlw[r0*QSd+kk];     al[1]=Qlw[(r0+8)*QSd+kk];
                al[2]=Qlw[r0*QSd+kk+4];   al[3]=Qlw[(r0+8)*QSd+kk+4];
                #pragma unroll
                for (int nt=0;nt<4;nt++){
                    int c = nt*8 + r0;
                    uint32_t bh_[2] = { Kh[c*KSd+kk], Kh[c*KSd+kk+4] };
                    uint32_t bl_[2] = { Kl[c*KSd+kk], Kl[c*KSd+kk+4] };
                    mma8(accS[nt], ah, bh_);
                    mma8(accS[nt], ah, bl_);
                    mma8(accS[nt], al, bh_);
                }
            }

            // scale + warp-local online softmax
            #pragma unroll
            for (int nt=0;nt<4;nt++)
                #pragma unroll
                for (int t=0;t<4;t++) accS[nt][t] *= SCALE;

            float m0 = -1e30f, m1 = -1e30f;
            #pragma unroll
            for (int nt=0;nt<4;nt++){
                m0 = fmaxf(m0, fmaxf(accS[nt][0], accS[nt][1]));
                m1 = fmaxf(m1, fmaxf(accS[nt][2], accS[nt][3]));
            }
            m0 = fmaxf(m0, __shfl_xor_sync(0xffffffffu, m0, 1));
            m0 = fmaxf(m0, __shfl_xor_sync(0xffffffffu, m0, 2));
            m1 = fmaxf(m1, __shfl_xor_sync(0xffffffffu, m1, 1));
            m1 = fmaxf(m1, __shfl_xor_sync(0xffffffffu, m1, 2));
            float mnew0 = fmaxf(rm0, m0);
            float mnew1 = fmaxf(rm1, m1);
            float al0 = __expf(rm0 - mnew0);
            float al1 = __expf(rm1 - mnew1);

            float s0 = 0.f, s1 = 0.f;
            #pragma unroll
            for (int nt=0;nt<4;nt++){
                float p0 = __expf(accS[nt][0] - mnew0);
                float p1 = __expf(accS[nt][1] - mnew0);
                float p2 = __expf(accS[nt][2] - mnew1);
                float p3 = __expf(accS[nt][3] - mnew1);
                s0 += p0 + p1; s1 += p2 + p3;
                int c = nt*8 + j*2;
                *(uint2*)(&Pww[r0*PSd + c])     = make_uint2(cvt_tf32(p0), cvt_tf32(p1));
                *(uint2*)(&Pww[(r0+8)*PSd + c]) = make_uint2(cvt_tf32(p2), cvt_tf32(p3));
            }
            s0 += __shfl_xor_sync(0xffffffffu, s0, 1);
            s0 += __shfl_xor_sync(0xffffffffu, s0, 2);
            s1 += __shfl_xor_sync(0xffffffffu, s1, 1);
            s1 += __shfl_xor_sync(0xffffffffu, s1, 2);
            rl0 = rl0*al0 + s0;
            rl1 = rl1*al1 + s1;
            rm0 = mnew0; rm1 = mnew1;

            // rescale accO
            #pragma unroll
            for (int nt=0;nt<16;nt++){
                accO[nt][0]*=al0; accO[nt][1]*=al0;
                accO[nt][2]*=al1; accO[nt][3]*=al1;
            }
            __syncwarp();

            // PV (1xTF32): warp tile 16x128 over k=32
            #pragma unroll
            for (int kg=0; kg<4; kg++){
                int kk = kg*8 + j;
                uint32_t ap[4];
                ap[0] = Pww[r0*PSd + kk];
                ap[1] = Pww[(r0+8)*PSd + kk];
                ap[2] = Pww[r0*PSd + kk + 4];
                ap[3] = Pww[(r0+8)*PSd + kk + 4];
                #pragma unroll
                for (int nt2=0; nt2<16; nt2++){
                    int c = nt2*8 + r0;
                    uint32_t bp[2] = { Vt[kk*VSd + c], Vt[(kk+4)*VSd + c] };
                    mma8(accO[nt2], ap, bp);
                }
            }
            asm volatile("bar.arrive 2, 384;" ::: "memory");
        }

        // epilogue: x1 = x + O/l
        float i0 = 1.f/rl0, i1 = 1.f/rl1;
        long grow = (long)b*Tn + q0 + wid*16 + r0;
        #pragma unroll
        for (int nt2=0; nt2<16; nt2++){
            int c = h*Dn + nt2*8 + j*2;
            long o0 = grow*Cn + c, o1 = (grow+8)*Cn + c;
            float2 v0 = make_float2(accO[nt2][0]*i0 + x[o0], accO[nt2][1]*i0 + x[o0+1]);
            float2 v1 = make_float2(accO[nt2][2]*i1 + x[o1], accO[nt2][3]*i1 + x[o1+1]);
            *(float2*)(x1 + o0) = v0;
            *(float2*)(x1 + o1) = v1;
        }
    }
}

// ---------------- host launcher ----------------
extern "C" void kernel_launch(void* const* d_in, const int* in_sizes, int n_in,
                              void* d_out, int out_size)
{
    const float* x    = (const float*)d_in[0];
    const float* wq   = (const float*)d_in[1];
    const float* wk   = (const float*)d_in[2];
    const float* wv   = (const float*)d_in[3];
    const float* w1   = (const float*)d_in[4];
    const float* b1   = (const float*)d_in[5];
    const float* w2   = (const float*)d_in[6];
    const float* b2   = (const float*)d_in[7];
    const float* ln1g = (const float*)d_in[8];
    const float* ln1b = (const float*)d_in[9];
    const float* ln2g = (const float*)d_in[10];
    const float* ln2b = (const float*)d_in[11];
    float* out = (float*)d_out;

    float *h, *q, *k, *v, *x1, *h2, *ff;
    cudaGetSymbolAddress((void**)&h,  g_h);
    cudaGetSymbolAddress((void**)&q,  g_q);
    cudaGetSymbolAddress((void**)&k,  g_k);
    cudaGetSymbolAddress((void**)&v,  g_v);
    cudaGetSymbolAddress((void**)&x1, g_x1);
    cudaGetSymbolAddress((void**)&h2, g_h2);
    cudaGetSymbolAddress((void**)&ff, g_ff);

    const int SM1 = 2*(2048+2112)*4;
    const int SM3 = 2*(2*2048+2*2112)*4;

    cudaFuncSetAttribute(attn_ws, cudaFuncAttributeMaxDynamicSharedMemorySize,
                         ATTN_BYTES);
    cudaFuncSetAttribute(mma_gemm<1>, cudaFuncAttributeMaxDynamicSharedMemorySize, SM1);
    cudaFuncSetAttribute(mma_gemm<3>, cudaFuncAttributeMaxDynamicSharedMemorySize, SM3);

    // 1) LN1
    ln_kernel<<<Mrows, 256>>>(x, ln1g, ln1b, h);

    // 2) projections: q,k in 3xTF32 (score chain), v in 1xTF32
    dim3 pg(1, Mrows/128, Hn);
    mma_gemm<3><<<pg, 256, SM3>>>(h, wq, q, Mrows, Dn, Cn, Cn, Dn, Cn,
                             (long)Cn*Dn, (long)Dn, nullptr, 0, nullptr, 0);
    mma_gemm<3><<<pg, 256, SM3>>>(h, wk, k, Mrows, Dn, Cn, Cn, Dn, Cn,
                             (long)Cn*Dn, (long)Dn, nullptr, 0, nullptr, 0);
    mma_gemm<1><<<pg, 256, SM1>>>(h, wv, v, Mrows, Dn, Cn, Cn, Dn, Cn,
                             (long)Cn*Dn, (long)Dn, nullptr, 0, nullptr, 0);

    // 3) attention + residual (warp-specialized, 128-row Q tiles, 512 CTAs)
    attn_ws<<<dim3(Tn/QTrows, Bsz*Hn), 384, ATTN_BYTES>>>(q, k, v, x, x1);

    // 4) LN2
    ln_kernel<<<Mrows, 256>>>(x1, ln2g, ln2b, h2);

    // 5) FF1: relu(h2 @ w1 + b1)
    mma_gemm<1><<<dim3(DffN/128, Mrows/128, 1), 256, SM1>>>(h2, w1, ff, Mrows, DffN, Cn,
                             Cn, DffN, DffN, 0L, 0L, b1, 1, nullptr, 0);

    // 6) FF2: out = x1 + (ff @ w2 + b2)
    mma_gemm<1><<<dim3(Cn/128, Mrows/128, 1), 256, SM1>>>(ff, w2, out, Mrows, Cn, DffN,
                             DffN, Cn, Cn, 0L, 0L, b2, 0, x1, Cn);
}

// round 17
// speedup vs baseline: 1.1340x; 1.1340x over previous
#include <cuda_runtime.h>
#include <cuda_bf16.h>
#include <math.h>
#include <stdint.h>

// Problem constants
#define Bsz 4
#define Tn  2048
#define Cn  1024
#define Hn  8
#define Dn  128
#define DffN 4096
#define Mrows (Bsz*Tn)   // 8192
#define SCALE 11.313708498984761f  // sqrt(128), multiply (faithful to reference)

// ---------------- scratch ----------------
__device__ float g_h [(size_t)Mrows*Cn];
__device__ float g_q [(size_t)Mrows*Cn];
__device__ float g_k [(size_t)Mrows*Cn];
__device__ float g_v [(size_t)Mrows*Cn];
__device__ float g_x1[(size_t)Mrows*Cn];
__device__ float g_h2[(size_t)Mrows*Cn];
__device__ float g_ff[(size_t)Mrows*DffN];

// ---------------- helpers ----------------
__device__ __forceinline__ uint32_t cvt_tf32(float x){
    uint32_t u; asm("cvt.rna.tf32.f32 %0, %1;" : "=r"(u) : "f"(x)); return u;
}
__device__ __forceinline__ void mma8(float* d, const uint32_t* a, const uint32_t* b){
    asm volatile("mma.sync.aligned.m16n8k8.row.col.f32.tf32.tf32.f32 "
        "{%0,%1,%2,%3},{%4,%5,%6,%7},{%8,%9},{%0,%1,%2,%3};"
        : "+f"(d[0]),"+f"(d[1]),"+f"(d[2]),"+f"(d[3])
        : "r"(a[0]),"r"(a[1]),"r"(a[2]),"r"(a[3]),"r"(b[0]),"r"(b[1]));
}
__device__ __forceinline__ void mma16(float* d, const uint32_t* a, const uint32_t* b){
    asm volatile("mma.sync.aligned.m16n8k16.row.col.f32.bf16.bf16.f32 "
        "{%0,%1,%2,%3},{%4,%5,%6,%7},{%8,%9},{%0,%1,%2,%3};"
        : "+f"(d[0]),"+f"(d[1]),"+f"(d[2]),"+f"(d[3])
        : "r"(a[0]),"r"(a[1]),"r"(a[2]),"r"(a[3]),"r"(b[0]),"r"(b[1]));
}
// pack two floats as bf16x2: element0(low half)=e0 (k even), element1=e1 (k odd)
__device__ __forceinline__ uint32_t pack_bf2(float e0, float e1){
    __nv_bfloat162 t = __floats2bfloat162_rn(e0, e1);
    return *(uint32_t*)&t;
}
__device__ __forceinline__ float bf_hi(float x){
    return __bfloat162float(__float2bfloat16_rn(x));
}

// ---------------- LayerNorm ----------------
__global__ __launch_bounds__(256) void ln_kernel(
    const float* __restrict__ x, const float* __restrict__ g,
    const float* __restrict__ bta, float* __restrict__ out)
{
    long row = blockIdx.x;
    int tid = threadIdx.x;
    const float4* xr = (const float4*)(x + row*(long)Cn);
    float4 v = xr[tid];
    float s = v.x + v.y + v.z + v.w;

    __shared__ float sh[34];
    int lane = tid & 31, wid = tid >> 5;
    #pragma unroll
    for (int o = 16; o > 0; o >>= 1) s += __shfl_xor_sync(0xffffffffu, s, o);
    if (lane == 0) sh[wid] = s;
    __syncthreads();
    if (tid == 0) {
        float t = 0.f;
        #pragma unroll
        for (int w = 0; w < 8; w++) t += sh[w];
        sh[32] = t * (1.0f / Cn);
    }
    __syncthreads();
    float mu = sh[32];
    float dx0 = v.x - mu, dx1 = v.y - mu, dx2 = v.z - mu, dx3 = v.w - mu;
    float ss = dx0*dx0 + dx1*dx1 + dx2*dx2 + dx3*dx3;
    #pragma unroll
    for (int o = 16; o > 0; o >>= 1) ss += __shfl_xor_sync(0xffffffffu, ss, o);
    __syncthreads();
    if (lane == 0) sh[wid] = ss;
    __syncthreads();
    if (tid == 0) {
        float t = 0.f;
        #pragma unroll
        for (int w = 0; w < 8; w++) t += sh[w];
        sh[33] = rsqrtf(t * (1.0f / Cn) + 1e-5f);
    }
    __syncthreads();
    float rstd = sh[33];
    float4 gg = ((const float4*)g)[tid];
    float4 bb = ((const float4*)bta)[tid];
    float4 o4;
    o4.x = dx0 * rstd * gg.x + bb.x;
    o4.y = dx1 * rstd * gg.y + bb.y;
    o4.z = dx2 * rstd * gg.z + bb.z;
    o4.w = dx3 * rstd * gg.w + bb.w;
    ((float4*)(out + row*(long)Cn))[tid] = o4;
}

// ---------------- TF32 MMA GEMM (round-8 proven; used for V-proj + FFN) ----------------
template<int SPLIT>
__global__ __launch_bounds__(256, 2) void mma_gemm(
    const float* __restrict__ A, const float* __restrict__ Bm, float* __restrict__ Cm,
    int M, int N, int K, int lda, int ldb, int ldc,
    long sB, long sC,
    const float* __restrict__ bias, int applyRelu,
    const float* __restrict__ res, int ldres)
{
    constexpr int AW = 2048;
    constexpr int BW = 2112;
    constexpr int oAl = AW;
    constexpr int oBh = (SPLIT==3) ? 2*AW : AW;
    constexpr int oBl = oBh + BW;
    constexpr int NTW = (SPLIT==3) ? (2*AW + 2*BW) : (AW + BW);
    extern __shared__ uint32_t smem[];

    int bz = blockIdx.z;
    Bm += bz * sB;
    Cm += bz * sC;

    int brow = blockIdx.y*128, bcol = blockIdx.x*128;
    int tid = threadIdx.x, lane = tid&31, wid = tid>>5;
    int wm = wid>>2, wn = wid&3;
    int lsw = lane ^ (lane>>2);

    float acc[4][4][4];
    #pragma unroll
    for (int i=0;i<4;i++)
        #pragma unroll
        for (int j=0;j<4;j++)
            #pragma unroll
            for (int t=0;t<4;t++) acc[i][j][t]=0.f;

    int a_r0 = tid>>2;
    int a_k0 = (tid&3)*4;
    const float* Ap = A + (long)(brow + a_r0)*lda + a_k0;
    int b_k0 = tid>>5;
    int b_c0 = lane*4;
    const float* Bp = Bm + (long)b_k0*ldb + bcol + b_c0;

    float4 av0, av1, bv0, bv1;

    auto gload = [&](){
        av0 = *(const float4*)(Ap);
        av1 = *(const float4*)(Ap + (long)64*lda);
        bv0 = *(const float4*)(Bp);
        bv1 = *(const float4*)(Bp + (long)8*ldb);
        Ap += 16; Bp += (long)16*ldb;
    };

    int st_rr  = a_r0 & 15;
    int st_r4a = a_r0 >> 4;
    int st_r4b = (a_r0 + 64) >> 4;
    int st_wk  = (tid & 1) * 2;
    int st_rb  = (st_rr >> 3) & 1;
    int st_bk3 = b_k0 & 3;
    int st_bw  = (b_k0 >> 2) & 1;

    auto store_tile = [&](uint32_t* base){
        uint32_t* Ah = base;
        uint32_t* Al = base + oAl;
        uint32_t* Bh = base + oBh;
        uint32_t* Bl = base + oBl;
        float va[4] = {av0.x,av0.y,av0.z,av0.w};
        float vb[4] = {av1.x,av1.y,av1.z,av1.w};
        #pragma unroll
        for (int j=0;j<4;j++){
            int k  = a_k0 + j;
            int l  = ((st_rr&7)<<2) | j;
            int ls = l ^ (st_rr&7);
            int w  = st_wk + st_rb;
            int idA = (k>>3)*1024 + ls*4 + w;
            uint32_t h0 = cvt_tf32(va[j]);
            Ah[idA + st_r4a*128] = h0;
            uint32_t h1 = cvt_tf32(vb[j]);
            Ah[idA + st_r4b*128] = h1;
            if (SPLIT==3){
                Al[idA + st_r4a*128] = cvt_tf32(va[j]-__uint_as_float(h0));
                Al[idA + st_r4b*128] = cvt_tf32(vb[j]-__uint_as_float(h1));
            }
        }
        float wa[4] = {bv0.x,bv0.y,bv0.z,bv0.w};
        float wb[4] = {bv1.x,bv1.y,bv1.z,bv1.w};
        #pragma unroll
        for (int j=0;j<4;j++){
            int n = b_c0 + j;
            int l = ((n&7)<<2) | st_bk3;
            int idB = (n>>3)*66 + l*2 + st_bw;
            uint32_t h0 = cvt_tf32(wa[j]);
            Bh[idB] = h0;
            uint32_t h1 = cvt_tf32(wb[j]);
            Bh[idB + 1056] = h1;
            if (SPLIT==3){
                Bl[idB]        = cvt_tf32(wa[j]-__uint_as_float(h0));
                Bl[idB + 1056] = cvt_tf32(wb[j]-__uint_as_float(h1));
            }
        }
    };

    auto compute_tile = [&](const uint32_t* base){
        const uint32_t* Ah = base;
        const uint32_t* Bh = base + oBh;
        #pragma unroll
        for (int kg = 0; kg < 2; kg++){
            uint32_t bhf[4][2];
            #pragma unroll
            for (int nt=0;nt<4;nt++){
                uint2 t = *(const uint2*)(Bh + kg*1056 + (wn*4+nt)*66 + lane*2);
                bhf[nt][0]=t.x; bhf[nt][1]=t.y;
            }
            #pragma unroll
            for (int mt=0;mt<4;mt++){
                uint4 a4 = *(const uint4*)(Ah + kg*1024 + (wm*4+mt)*128 + lsw*4);
                uint32_t ah[4] = {a4.x,a4.y,a4.z,a4.w};
                #pragma unroll
                for (int nt=0;nt<4;nt++){
                    mma8(acc[mt][nt], ah, bhf[nt]);
                }
            }
        }
    };

    gload();
    store_tile(smem);
    __syncthreads();

    int nIter = K >> 4;
    for (int i = 0; i < nIter; i++) {
        uint32_t* cur = smem + (size_t)(i & 1) * NTW;
        uint32_t* nxt = smem + (size_t)((i & 1) ^ 1) * NTW;
        bool hasNext = (i + 1 < nIter);
        if (hasNext) gload();
        compute_tile(cur);
        if (hasNext) store_tile(nxt);
        __syncthreads();
    }

    #pragma unroll
    for (int mt=0;mt<4;mt++){
        int r0 = brow + wm*64 + mt*16 + (lane>>2);
        #pragma unroll
        for (int nt=0;nt<4;nt++){
            int c = bcol + wn*32 + nt*8 + (lane&3)*2;
            float2 v0 = make_float2(acc[mt][nt][0], acc[mt][nt][1]);
            float2 v1 = make_float2(acc[mt][nt][2], acc[mt][nt][3]);
            if (bias){
                float b0=bias[c], b1=bias[c+1];
                v0.x+=b0; v0.y+=b1; v1.x+=b0; v1.y+=b1;
            }
            if (applyRelu){
                v0.x=fmaxf(v0.x,0.f); v0.y=fmaxf(v0.y,0.f);
                v1.x=fmaxf(v1.x,0.f); v1.y=fmaxf(v1.y,0.f);
            }
            if (res){
                v0.x += res[(long)r0*ldres + c];     v0.y += res[(long)r0*ldres + c+1];
                v1.x += res[(long)(r0+8)*ldres + c]; v1.y += res[(long)(r0+8)*ldres + c+1];
            }
            *(float2*)(Cm + (long)r0*ldc + c)     = v0;
            *(float2*)(Cm + (long)(r0+8)*ldc + c) = v1;
        }
    }
}

// ---------------- 3xBF16 MMA GEMM (m16n8k16): q/k projections ----------------
// 128x128 tile, BK=16 (one k16 step/iter), 256 thr, ping-pong buffers.
// A pairs: Ahp[w*136 + r] (w = k/2, 0..7). B pairs: Bhp[n*12 + w].
#define BF_AW (8*136)     // 1088 words per plane
#define BF_BW (128*12)    // 1536 words per plane
#define BF_NTW (2*BF_AW + 2*BF_BW)   // 5248 per buffer
#define BF_SMEM (2*BF_NTW*4)         // 41984 B

__global__ __launch_bounds__(256, 2) void mma_gemm_bf3(
    const float* __restrict__ A, const float* __restrict__ Bm, float* __restrict__ Cm,
    int M, int N, int K, int lda, int ldb, int ldc,
    long sB, long sC)
{
    extern __shared__ uint32_t smem[];

    int bz = blockIdx.z;
    Bm += bz * sB;
    Cm += bz * sC;

    int brow = blockIdx.y*128, bcol = blockIdx.x*128;
    int tid = threadIdx.x, lane = tid&31, wid = tid>>5;
    int wm = wid>>2, wn = wid&3;
    int j = lane&3, r0l = lane>>2;

    float acc[4][4][4];
    #pragma unroll
    for (int i=0;i<4;i++)
        #pragma unroll
        for (int jj=0;jj<4;jj++)
            #pragma unroll
            for (int t=0;t<4;t++) acc[i][jj][t]=0.f;

    int a_r0 = tid>>2;
    int a_k0 = (tid&3)*4;
    const float* Ap = A + (long)(brow + a_r0)*lda + a_k0;
    int b_k0 = tid>>5;                 // pair-row 0..7 (k rows 2*b_k0, 2*b_k0+1)
    int b_c0 = lane*4;
    const float* Bp = Bm + (long)(2*b_k0)*ldb + bcol + b_c0;

    float4 av0, av1, bv0, bv1;
    auto gload = [&](){
        av0 = *(const float4*)(Ap);
        av1 = *(const float4*)(Ap + (long)64*lda);
        bv0 = *(const float4*)(Bp);
        bv1 = *(const float4*)(Bp + (long)ldb);
        Ap += 16; Bp += (long)16*ldb;
    };

    auto store_tile = [&](uint32_t* base){
        uint32_t* Ahp = base;
        uint32_t* Alp = base + BF_AW;
        uint32_t* Bhp = base + 2*BF_AW;
        uint32_t* Blp = base + 2*BF_AW + BF_BW;
        int w0 = a_k0 >> 1;            // pair-word index (0,2,4,6)
        {
            float v[4] = {av0.x,av0.y,av0.z,av0.w};
            float h0=bf_hi(v[0]), h1=bf_hi(v[1]), h2=bf_hi(v[2]), h3=bf_hi(v[3]);
            Ahp[w0*136 + a_r0]     = pack_bf2(h0,h1);
            Ahp[(w0+1)*136 + a_r0] = pack_bf2(h2,h3);
            Alp[w0*136 + a_r0]     = pack_bf2(v[0]-h0, v[1]-h1);
            Alp[(w0+1)*136 + a_r0] = pack_bf2(v[2]-h2, v[3]-h3);
        }
        {
            float v[4] = {av1.x,av1.y,av1.z,av1.w};
            float h0=bf_hi(v[0]), h1=bf_hi(v[1]), h2=bf_hi(v[2]), h3=bf_hi(v[3]);
            int r = a_r0 + 64;
            Ahp[w0*136 + r]     = pack_bf2(h0,h1);
            Ahp[(w0+1)*136 + r] = pack_bf2(h2,h3);
            Alp[w0*136 + r]     = pack_bf2(v[0]-h0, v[1]-h1);
            Alp[(w0+1)*136 + r] = pack_bf2(v[2]-h2, v[3]-h3);
        }
        {
            float a0[4] = {bv0.x,bv0.y,bv0.z,bv0.w};   // k = 2*b_k0
            float a1[4] = {bv1.x,bv1.y,bv1.z,bv1.w};   // k = 2*b_k0+1
            #pragma unroll
            for (int t=0;t<4;t++){
                int n = b_c0 + t;
                float h0 = bf_hi(a0[t]), h1 = bf_hi(a1[t]);
                Bhp[n*12 + b_k0] = pack_bf2(h0, h1);
                Blp[n*12 + b_k0] = pack_bf2(a0[t]-h0, a1[t]-h1);
            }
        }
    };

    auto compute_tile = [&](const uint32_t* base){
        const uint32_t* Ahp = base;
        const uint32_t* Alp = base + BF_AW;
        const uint32_t* Bhp = base + 2*BF_AW;
        const uint32_t* Blp = base + 2*BF_AW + BF_BW;
        uint32_t bhf[4][2], blf[4][2];
        #pragma unroll
        for (int nt=0;nt<4;nt++){
            int c = wn*32 + nt*8 + r0l;
            bhf[nt][0] = Bhp[c*12 + j];
            bhf[nt][1] = Bhp[c*12 + j + 4];
            blf[nt][0] = Blp[c*12 + j];
            blf[nt][1] = Blp[c*12 + j + 4];
        }
        #pragma unroll
        for (int mt=0;mt<4;mt++){
            int m = wm*64 + mt*16 + r0l;
            uint32_t ah[4], al[4];
            ah[0] = Ahp[j*136 + m];       ah[1] = Ahp[j*136 + m + 8];
            ah[2] = Ahp[(j+4)*136 + m];   ah[3] = Ahp[(j+4)*136 + m + 8];
            al[0] = Alp[j*136 + m];       al[1] = Alp[j*136 + m + 8];
            al[2] = Alp[(j+4)*136 + m];   al[3] = Alp[(j+4)*136 + m + 8];
            #pragma unroll
            for (int nt=0;nt<4;nt++){
                mma16(acc[mt][nt], ah, bhf[nt]);
                mma16(acc[mt][nt], ah, blf[nt]);
                mma16(acc[mt][nt], al, bhf[nt]);
            }
        }
    };

    gload();
    store_tile(smem);
    __syncthreads();

    int nIter = K >> 4;
    for (int i = 0; i < nIter; i++) {
        uint32_t* cur = smem + (size_t)(i & 1) * BF_NTW;
        uint32_t* nxt = smem + (size_t)((i & 1) ^ 1) * BF_NTW;
        bool hasNext = (i + 1 < nIter);
        if (hasNext) gload();
        compute_tile(cur);
        if (hasNext) store_tile(nxt);
        __syncthreads();
    }

    #pragma unroll
    for (int mt=0;mt<4;mt++){
        int r0 = brow + wm*64 + mt*16 + r0l;
        #pragma unroll
        for (int nt=0;nt<4;nt++){
            int c = bcol + wn*32 + nt*8 + j*2;
            *(float2*)(Cm + (long)r0*ldc + c)     = make_float2(acc[mt][nt][0], acc[mt][nt][1]);
            *(float2*)(Cm + (long)(r0+8)*ldc + c) = make_float2(acc[mt][nt][2], acc[mt][nt][3]);
        }
    }
}

// ---------------- Warp-specialized flash attention (r13 skeleton, 3xBF16 QK) ----------------
// warps 0-3 consumers (16 Q rows), warps 4-7 producers (32-row K/V double-buffered).
// Q/K stored as bf16 PAIR words (hi & lo planes). PV stays 1xTF32 (r13 path).
#define QS2 68
#define KS2 68
#define VSd 136
#define PSd 36
#define QH_OFF 0
#define QL_OFF (64*QS2)                  // 4352
#define KH_OFF (2*64*QS2)                // 8704
#define KL_OFF (KH_OFF + 2*32*KS2)       // 13056
#define VT_OFF (KL_OFF + 2*32*KS2)       // 17408
#define PW_OFF (VT_OFF + 2*32*VSd)       // 26112
#define ATTN_WORDS (PW_OFF + 4*16*PSd)   // 28416
#define ATTN_BYTES (ATTN_WORDS*4)        // 113664 B

__global__ __launch_bounds__(256, 1) void attn_ws(
    const float* __restrict__ Q, const float* __restrict__ K, const float* __restrict__ V,
    const float* __restrict__ x, float* __restrict__ x1)
{
    extern __shared__ uint32_t sm[];
    uint32_t* Qh = sm + QH_OFF;
    uint32_t* Ql = sm + QL_OFF;
    uint32_t* Kh = sm + KH_OFF;
    uint32_t* Kl = sm + KL_OFF;
    uint32_t* Vt = sm + VT_OFF;
    uint32_t* Pw = sm + PW_OFF;

    int bh = blockIdx.y; int b = bh>>3, h = bh&7;
    int q0 = blockIdx.x*64;
    int tid = threadIdx.x, lane = tid&31, wid = tid>>5;

    const float* Qg = Q + ((long)b*Tn + q0)*Cn + h*Dn;
    const float* Kg = K + (long)b*Tn*Cn + h*Dn;
    const float* Vg = V + (long)b*Tn*Cn + h*Dn;

    // All 256 threads: load + bf16-split Q tile (64x128) into pair-word planes
    #pragma unroll
    for (int it=0; it<8; it++){
        int idx = tid + it*256;
        int r = idx>>5, c4 = (idx&31)*4, w = (idx&31)*2;
        float4 t = *(const float4*)(Qg + (long)r*Cn + c4);
        float h0=bf_hi(t.x), h1=bf_hi(t.y), h2=bf_hi(t.z), h3=bf_hi(t.w);
        *(uint2*)(&Qh[r*QS2 + w]) = make_uint2(pack_bf2(h0,h1), pack_bf2(h2,h3));
        *(uint2*)(&Ql[r*QS2 + w]) = make_uint2(pack_bf2(t.x-h0, t.y-h1),
                                               pack_bf2(t.z-h2, t.w-h3));
    }
    __syncthreads();

    if (wid >= 4) {
        // ================= PRODUCER =================
        int p = tid - 128;   // 0..127
        for (int kt = 0; kt < Tn/32; kt++){
            int buf = kt & 1;
            if (kt >= 2)
                asm volatile("bar.sync %0, 256;" :: "r"(3+buf) : "memory");
            const float* Ksrc = Kg + (long)kt*32*Cn;
            const float* Vsrc = Vg + (long)kt*32*Cn;
            float4 kr[8], vr[8];
            #pragma unroll
            for (int i=0;i<8;i++){
                int idx = p + i*128;
                int r = idx>>5, c = (idx&31)*4;
                kr[i] = *(const float4*)(Ksrc + (long)r*Cn + c);
                vr[i] = *(const float4*)(Vsrc + (long)r*Cn + c);
            }
            uint32_t* Khb = Kh + buf*(32*KS2);
            uint32_t* Klb = Kl + buf*(32*KS2);
            uint32_t* Vtb = Vt + buf*(32*VSd);
            #pragma unroll
            for (int i=0;i<8;i++){
                int idx = p + i*128;
                int r = idx>>5, c = (idx&31)*4, w = (idx&31)*2;
                float h0=bf_hi(kr[i].x), h1=bf_hi(kr[i].y), h2=bf_hi(kr[i].z), h3=bf_hi(kr[i].w);
                *(uint2*)(&Khb[r*KS2 + w]) = make_uint2(pack_bf2(h0,h1), pack_bf2(h2,h3));
                *(uint2*)(&Klb[r*KS2 + w]) = make_uint2(pack_bf2(kr[i].x-h0, kr[i].y-h1),
                                                        pack_bf2(kr[i].z-h2, kr[i].w-h3));
                uint4 vv;
                vv.x=cvt_tf32(vr[i].x); vv.y=cvt_tf32(vr[i].y);
                vv.z=cvt_tf32(vr[i].z); vv.w=cvt_tf32(vr[i].w);
                *(uint4*)(&Vtb[r*VSd + c]) = vv;
            }
            asm volatile("bar.arrive %0, 256;" :: "r"(1+buf) : "memory");
        }
    } else {
        // ================= CONSUMER =================
        int r0 = lane>>2, j = lane&3;
        const uint32_t* Qhw = Qh + (wid*16)*QS2;
        const uint32_t* Qlw = Ql + (wid*16)*QS2;
        uint32_t* Pww = Pw + wid*(16*PSd);

        float accO[16][4];
        #pragma unroll
        for (int i=0;i<16;i++)
            #pragma unroll
            for (int t=0;t<4;t++) accO[i][t]=0.f;
        float rm0 = -1e30f, rm1 = -1e30f, rl0 = 0.f, rl1 = 0.f;

        for (int kt = 0; kt < Tn/32; kt++){
            int buf = kt & 1;
            asm volatile("bar.sync %0, 256;" :: "r"(1+buf) : "memory");
            const uint32_t* Khb = Kh + buf*(32*KS2);
            const uint32_t* Klb = Kl + buf*(32*KS2);
            const uint32_t* Vtb = Vt + buf*(32*VSd);

            // S = Q K^T (3xBF16, m16n8k16): warp tile 16x32, 8 k16-groups
            float accS[4][4];
            #pragma unroll
            for (int i=0;i<4;i++)
                #pragma unroll
                for (int t=0;t<4;t++) accS[i][t]=0.f;

            #pragma unroll 4
            for (int kg=0; kg<8; kg++){
                int kw = kg*8 + j;
                uint32_t ah[4], al[4];
                ah[0]=Qhw[r0*QS2+kw];     ah[1]=Qhw[(r0+8)*QS2+kw];
                ah[2]=Qhw[r0*QS2+kw+4];   ah[3]=Qhw[(r0+8)*QS2+kw+4];
                al[0]=Qlw[r0*QS2+kw];     al[1]=Qlw[(r0+8)*QS2+kw];
                al[2]=Qlw[r0*QS2+kw+4];   al[3]=Qlw[(r0+8)*QS2+kw+4];
                #pragma unroll
                for (int nt=0;nt<4;nt++){
                    int c = nt*8 + r0;
                    uint32_t bh_[2] = { Khb[c*KS2+kw], Khb[c*KS2+kw+4] };
                    uint32_t bl_[2] = { Klb[c*KS2+kw], Klb[c*KS2+kw+4] };
                    mma16(accS[nt], ah, bh_);
                    mma16(accS[nt], ah, bl_);
                    mma16(accS[nt], al, bh_);
                }
            }

            // scale + warp-local online softmax (r13)
            #pragma unroll
            for (int nt=0;nt<4;nt++)
                #pragma unroll
                for (int t=0;t<4;t++) accS[nt][t] *= SCALE;

            float m0 = -1e30f, m1 = -1e30f;
            #pragma unroll
            for (int nt=0;nt<4;nt++){
                m0 = fmaxf(m0, fmaxf(accS[nt][0], accS[nt][1]));
                m1 = fmaxf(m1, fmaxf(accS[nt][2], accS[nt][3]));
            }
            m0 = fmaxf(m0, __shfl_xor_sync(0xffffffffu, m0, 1));
            m0 = fmaxf(m0, __shfl_xor_sync(0xffffffffu, m0, 2));
            m1 = fmaxf(m1, __shfl_xor_sync(0xffffffffu, m1, 1));
            m1 = fmaxf(m1, __shfl_xor_sync(0xffffffffu, m1, 2));
            float mnew0 = fmaxf(rm0, m0);
            float mnew1 = fmaxf(rm1, m1);
            float al0 = __expf(rm0 - mnew0);
            float al1 = __expf(rm1 - mnew1);

            float s0 = 0.f, s1 = 0.f;
            #pragma unroll
            for (int nt=0;nt<4;nt++){
                float p0 = __expf(accS[nt][0] - mnew0);
                float p1 = __expf(accS[nt][1] - mnew0);
                float p2 = __expf(accS[nt][2] - mnew1);
                float p3 = __expf(accS[nt][3] - mnew1);
                s0 += p0 + p1; s1 += p2 + p3;
                int c = nt*8 + j*2;
                *(uint2*)(&Pww[r0*PSd + c])     = make_uint2(cvt_tf32(p0), cvt_tf32(p1));
                *(uint2*)(&Pww[(r0+8)*PSd + c]) = make_uint2(cvt_tf32(p2), cvt_tf32(p3));
            }
            s0 += __shfl_xor_sync(0xffffffffu, s0, 1);
            s0 += __shfl_xor_sync(0xffffffffu, s0, 2);
            s1 += __shfl_xor_sync(0xffffffffu, s1, 1);
            s1 += __shfl_xor_sync(0xffffffffu, s1, 2);
            rl0 = rl0*al0 + s0;
            rl1 = rl1*al1 + s1;
            rm0 = mnew0; rm1 = mnew1;

            // rescale accO
            #pragma unroll
            for (int nt=0;nt<16;nt++){
                accO[nt][0]*=al0; accO[nt][1]*=al0;
                accO[nt][2]*=al1; accO[nt][3]*=al1;
            }
            __syncwarp();

            // PV (1xTF32, m16n8k8): warp tile 16x128 over k=32 (r13)
            #pragma unroll
            for (int kg=0; kg<4; kg++){
                int kk = kg*8 + j;
                uint32_t ap[4];
                ap[0] = Pww[r0*PSd + kk];
                ap[1] = Pww[(r0+8)*PSd + kk];
                ap[2] = Pww[r0*PSd + kk + 4];
                ap[3] = Pww[(r0+8)*PSd + kk + 4];
                #pragma unroll
                for (int nt2=0; nt2<16; nt2++){
                    int c = nt2*8 + r0;
                    uint32_t bp[2] = { Vtb[kk*VSd + c], Vtb[(kk+4)*VSd + c] };
                    mma8(accO[nt2], ap, bp);
                }
            }
            asm volatile("bar.arrive %0, 256;" :: "r"(3+buf) : "memory");
        }

        // epilogue: x1 = x + O/l
        float i0 = 1.f/rl0, i1 = 1.f/rl1;
        long grow = (long)b*Tn + q0 + wid*16 + r0;
        #pragma unroll
        for (int nt2=0; nt2<16; nt2++){
            int c = h*Dn + nt2*8 + j*2;
            long o0 = grow*Cn + c, o1 = (grow+8)*Cn + c;
            float2 v0 = make_float2(accO[nt2][0]*i0 + x[o0], accO[nt2][1]*i0 + x[o0+1]);
            float2 v1 = make_float2(accO[nt2][2]*i1 + x[o1], accO[nt2][3]*i1 + x[o1+1]);
            *(float2*)(x1 + o0) = v0;
            *(float2*)(x1 + o1) = v1;
        }
    }
}

// ---------------- host launcher ----------------
extern "C" void kernel_launch(void* const* d_in, const int* in_sizes, int n_in,
                              void* d_out, int out_size)
{
    const float* x    = (const float*)d_in[0];
    const float* wq   = (const float*)d_in[1];
    const float* wk   = (const float*)d_in[2];
    const float* wv   = (const float*)d_in[3];
    const float* w1   = (const float*)d_in[4];
    const float* b1   = (const float*)d_in[5];
    const float* w2   = (const float*)d_in[6];
    const float* b2   = (const float*)d_in[7];
    const float* ln1g = (const float*)d_in[8];
    const float* ln1b = (const float*)d_in[9];
    const float* ln2g = (const float*)d_in[10];
    const float* ln2b = (const float*)d_in[11];
    float* out = (float*)d_out;

    float *h, *q, *k, *v, *x1, *h2, *ff;
    cudaGetSymbolAddress((void**)&h,  g_h);
    cudaGetSymbolAddress((void**)&q,  g_q);
    cudaGetSymbolAddress((void**)&k,  g_k);
    cudaGetSymbolAddress((void**)&v,  g_v);
    cudaGetSymbolAddress((void**)&x1, g_x1);
    cudaGetSymbolAddress((void**)&h2, g_h2);
    cudaGetSymbolAddress((void**)&ff, g_ff);

    const int SM1 = 2*(2048+2112)*4;

    cudaFuncSetAttribute(attn_ws, cudaFuncAttributeMaxDynamicSharedMemorySize,
                         ATTN_BYTES);
    cudaFuncSetAttribute(mma_gemm<1>, cudaFuncAttributeMaxDynamicSharedMemorySize, SM1);
    cudaFuncSetAttribute(mma_gemm_bf3, cudaFuncAttributeMaxDynamicSharedMemorySize, BF_SMEM);

    // 1) LN1
    ln_kernel<<<Mrows, 256>>>(x, ln1g, ln1b, h);

    // 2) projections: q,k in 3xBF16 (score chain), v in 1xTF32
    dim3 pg(1, Mrows/128, Hn);
    mma_gemm_bf3<<<pg, 256, BF_SMEM>>>(h, wq, q, Mrows, Dn, Cn, Cn, Dn, Cn,
                             (long)Cn*Dn, (long)Dn);
    mma_gemm_bf3<<<pg, 256, BF_SMEM>>>(h, wk, k, Mrows, Dn, Cn, Cn, Dn, Cn,
                             (long)Cn*Dn, (long)Dn);
    mma_gemm<1><<<pg, 256, SM1>>>(h, wv, v, Mrows, Dn, Cn, Cn, Dn, Cn,
                             (long)Cn*Dn, (long)Dn, nullptr, 0, nullptr, 0);

    // 3) attention + residual (warp-specialized, 3xBF16 QK)
    attn_ws<<<dim3(Tn/64, Bsz*Hn), 256, ATTN_BYTES>>>(q, k, v, x, x1);

    // 4) LN2
    ln_kernel<<<Mrows, 256>>>(x1, ln2g, ln2b, h2);

    // 5) FF1: relu(h2 @ w1 + b1)
    mma_gemm<1><<<dim3(DffN/128, Mrows/128, 1), 256, SM1>>>(h2, w1, ff, Mrows, DffN, Cn,
                             Cn, DffN, DffN, 0L, 0L, b1, 1, nullptr, 0);

    // 6) FF2: out = x1 + (ff @ w2 + b2)
    mma_gemm<1><<<dim3(Cn/128, Mrows/128, 1), 256, SM1>>>(ff, w2, out, Mrows, Cn, DffN,
                             DffN, Cn, Cn, 0L, 0L, b2, 0, x1, Cn);
}